// round 1
// baseline (speedup 1.0000x reference)
#include <cuda_runtime.h>
#include <cuda_bf16.h>

#define NN     5000   // nodes
#define TIN    12     // input timesteps
#define TTOT   24     // output timesteps
#define BB     16     // batch
#define CC     4      // channels
#define KNB    16     // neighbors
#define NH     4      // heads
#define DIN    48     // T*H
#define DOUT   12     // extrapolated steps

// Transposed x scratch: xt[n][t][b][c]  (15.36 MB, L2-resident)
__device__ float g_xt[(size_t)NN * TIN * BB * CC];

// ---------------------------------------------------------------------------
// Kernel 1: copy x (B,T,N,C) into out[:, 0:12, :, :]  — fully coalesced float4
// ---------------------------------------------------------------------------
__global__ void k_copy(const float* __restrict__ x, float* __restrict__ out) {
    int tid = blockIdx.x * blockDim.x + threadIdx.x;   // over B*T*N float4
    if (tid >= BB * TIN * NN) return;
    int n  = tid % NN;
    int bt = tid / NN;                 // b*TIN + t
    int b  = bt / TIN, t = bt % TIN;
    float4 v = ((const float4*)x)[tid];
    ((float4*)out)[((size_t)b * TTOT + t) * NN + n] = v;
}

// ---------------------------------------------------------------------------
// Kernel 2: transpose x (B,T,N,C) -> xt (N,T,B,C).  Writes coalesced.
// ---------------------------------------------------------------------------
__global__ void k_transpose(const float* __restrict__ x) {
    int tid = blockIdx.x * blockDim.x + threadIdx.x;   // over N*T*B float4
    if (tid >= NN * TIN * BB) return;
    int b  = tid % BB;
    int nt = tid / BB;                 // n*TIN + t
    int t  = nt % TIN, n = nt / TIN;
    ((float4*)g_xt)[tid] = ((const float4*)x)[((size_t)b * TIN + t) * NN + n];
}

// ---------------------------------------------------------------------------
// Kernel 3: per-node gather + head aggregation + 48x12 linear + ReLU
// Block per n, 64 threads = (b in 0..15) x (c in 0..3).
// ---------------------------------------------------------------------------
__global__ __launch_bounds__(64) void k_main(
    const float* __restrict__ dists,
    const float* __restrict__ W,
    const float* __restrict__ bias,
    const int*   __restrict__ neighbors,
    float* __restrict__ out)
{
    __shared__ float sw[KNB][NH];
    __shared__ int   snb[KNB];
    __shared__ float sW[DIN * DOUT];
    __shared__ float sb[DOUT];

    const int n   = blockIdx.x;
    const int tid = threadIdx.x;

    if (tid < KNB) {
        float d  = dists[n * KNB + tid];
        float e  = __expf(-d * d * (1.0f / 144.0f));   // sigma^2=36, H=4
        float e2 = e * e;
        sw[tid][0] = e;
        sw[tid][1] = e2;
        sw[tid][2] = e2 * e;
        sw[tid][3] = e2 * e2;
        snb[tid]   = neighbors[n * KNB + tid];
    }
    #pragma unroll
    for (int i = tid; i < DIN * DOUT; i += 64) sW[i] = W[i];
    if (tid < DOUT) sb[tid] = bias[tid];
    __syncthreads();

    const int b = tid >> 2;
    const int c = tid & 3;

    float acc[TIN][NH];
    #pragma unroll
    for (int t = 0; t < TIN; t++)
        #pragma unroll
        for (int h = 0; h < NH; h++) acc[t][h] = 0.0f;

    // Gather + aggregate. Each k reads one full 3KB neighbor row, coalesced
    // 128B per warp per (t): addr = ((j*TIN + t)*BB + b)*CC + c.
    #pragma unroll 1
    for (int k = 0; k < KNB; k++) {
        const int   j  = snb[k];
        const float w0 = sw[k][0], w1 = sw[k][1], w2 = sw[k][2], w3 = sw[k][3];
        const float* __restrict__ row = g_xt + ((size_t)j * TIN * BB + b) * CC + c;
        float xv[TIN];
        #pragma unroll
        for (int t = 0; t < TIN; t++) xv[t] = row[(size_t)t * BB * CC];
        #pragma unroll
        for (int t = 0; t < TIN; t++) {
            acc[t][0] = fmaf(xv[t], w0, acc[t][0]);
            acc[t][1] = fmaf(xv[t], w1, acc[t][1]);
            acc[t][2] = fmaf(xv[t], w2, acc[t][2]);
            acc[t][3] = fmaf(xv[t], w3, acc[t][3]);
        }
    }

    // Linear: y[o] = relu( sum_{t,h} acc[t][h] * W[t*NH+h][o] + bias[o] )
    float y[DOUT];
    #pragma unroll
    for (int o = 0; o < DOUT; o++) y[o] = sb[o];
    #pragma unroll
    for (int t = 0; t < TIN; t++) {
        #pragma unroll
        for (int h = 0; h < NH; h++) {
            const float a = acc[t][h];
            const float* __restrict__ wr = &sW[(t * NH + h) * DOUT];
            #pragma unroll
            for (int o = 0; o < DOUT; o++) y[o] = fmaf(a, wr[o], y[o]);
        }
    }

    // out[b][TIN+o][n][c]
    float* op = out + (((size_t)b * TTOT + TIN) * NN + n) * CC + c;
    #pragma unroll
    for (int o = 0; o < DOUT; o++)
        op[(size_t)o * NN * CC] = fmaxf(y[o], 0.0f);
}

// ---------------------------------------------------------------------------
extern "C" void kernel_launch(void* const* d_in, const int* in_sizes, int n_in,
                              void* d_out, int out_size)
{
    const float* x         = (const float*)d_in[0];
    const float* dists     = (const float*)d_in[1];
    const float* W         = (const float*)d_in[2];
    const float* bias      = (const float*)d_in[3];
    const int*   neighbors = (const int*)  d_in[4];
    float* out = (float*)d_out;

    {
        int total = BB * TIN * NN;                    // float4 elements
        int blk = 256, grd = (total + blk - 1) / blk;
        k_copy<<<grd, blk>>>(x, out);
    }
    {
        int total = NN * TIN * BB;                    // float4 elements
        int blk = 256, grd = (total + blk - 1) / blk;
        k_transpose<<<grd, blk>>>(x);
    }
    {
        k_main<<<NN, 64>>>(dists, W, bias, neighbors, out);
    }
}

// round 2
// speedup vs baseline: 1.1020x; 1.1020x over previous
#include <cuda_runtime.h>
#include <cuda_bf16.h>

#define NN     5000   // nodes
#define TIN    12     // input timesteps
#define TTOT   24     // output timesteps
#define BB     16     // batch
#define CC     4      // channels
#define KNB    16     // neighbors
#define NH     4      // heads
#define DIN    48     // T*H
#define DOUT   12     // extrapolated steps

// Transposed x scratch: xt[n][b][c][t]  (t fastest; 768 floats / 3KB per node)
__device__ float g_xt[(size_t)NN * BB * CC * TIN];

typedef unsigned long long ull;

__device__ __forceinline__ ull pk2(float lo, float hi) {
    ull r;
    asm("mov.b64 %0, {%1, %2};" : "=l"(r) : "f"(lo), "f"(hi));
    return r;
}
__device__ __forceinline__ void upk2(float& lo, float& hi, ull v) {
    asm("mov.b64 {%0, %1}, %2;" : "=f"(lo), "=f"(hi) : "l"(v));
}
__device__ __forceinline__ void fma2(ull& d, ull a, ull b, ull c) {
    asm("fma.rn.f32x2 %0, %1, %2, %3;" : "=l"(d) : "l"(a), "l"(b), "l"(c));
}

// ---------------------------------------------------------------------------
// Kernel A (fused): read x (B,T,N,C) once;
//   (1) copy into out[:, 0:12] (coalesced),
//   (2) transpose into g_xt[n][b][c][t] via smem tile (coalesced writes).
// Tile: 8 nodes per 256-thread block.
// ---------------------------------------------------------------------------
#define NT 8
#define SROW 772   // 768 floats per node + 4 pad (keeps 16B align, spreads banks)

__global__ __launch_bounds__(256) void k_prep(const float* __restrict__ x,
                                              float* __restrict__ out) {
    __shared__ __align__(16) float s[NT][SROW];

    const int tid = threadIdx.x;
    const int n0  = blockIdx.x * NT;
    const int nn  = tid & (NT - 1);
    const int mb  = tid >> 3;            // 0..31
    const int n   = n0 + nn;
    const bool valid = (n < NN);

    const float4* __restrict__ x4 = (const float4*)x;
    float4* __restrict__ out4 = (float4*)out;

    // Phase 1: 192 (b,t) rows x 8 nodes, coalesced reads of x
    #pragma unroll
    for (int i = 0; i < 6; i++) {
        int m = mb + (i << 5);           // 0..191, m = b*12 + t
        if (valid) {
            float4 v = x4[(size_t)m * NN + n];
            int b = m / TIN, t = m % TIN;
            out4[((size_t)b * TTOT + t) * NN + n] = v;   // copy half of output
            float* sp = &s[nn][b * 48 + t];              // [b][c][t] layout
            sp[0]  = v.x;
            sp[12] = v.y;
            sp[24] = v.z;
            sp[36] = v.w;
        }
    }
    __syncthreads();

    // Phase 2: write xt rows, fully coalesced (192 float4 per node)
    float4* __restrict__ xt4 = (float4*)g_xt;
    #pragma unroll
    for (int i = 0; i < 6; i++) {
        int g   = tid + (i << 8);        // 0..1535
        int nn2 = g / 192;
        int w   = g - nn2 * 192;
        int n2  = n0 + nn2;
        if (n2 < NN) {
            float4 v = *(const float4*)&s[nn2][w << 2];
            xt4[(size_t)n2 * 192 + w] = v;
        }
    }
}

// ---------------------------------------------------------------------------
// Kernel B: per-node gather + head aggregation + 48x12 linear + ReLU.
// Block per n, 64 threads = (b, c). All fp32 math through fma.rn.f32x2,
// packed over t-pairs (aggregation) and o-pairs (linear).
// ---------------------------------------------------------------------------
__global__ __launch_bounds__(64) void k_main(
    const float* __restrict__ dists,
    const float* __restrict__ W,
    const float* __restrict__ bias,
    const int*   __restrict__ neighbors,
    float* __restrict__ out)
{
    __shared__ float sw[KNB][NH];
    __shared__ int   snb[KNB];
    __shared__ __align__(16) float sW[DIN * DOUT];
    __shared__ float sb[DOUT];

    const int n   = blockIdx.x;
    const int tid = threadIdx.x;

    if (tid < KNB) {
        float d  = dists[n * KNB + tid];
        float e  = __expf(-d * d * (1.0f / 144.0f));   // sigma^2 = 36, H = 4
        float e2 = e * e;
        sw[tid][0] = e;
        sw[tid][1] = e2;
        sw[tid][2] = e2 * e;
        sw[tid][3] = e2 * e2;
        snb[tid]   = neighbors[n * KNB + tid];
    }
    #pragma unroll
    for (int i = tid; i < DIN * DOUT; i += 64) sW[i] = W[i];
    if (tid < DOUT) sb[tid] = bias[tid];
    __syncthreads();

    const int b = tid >> 2;
    const int c = tid & 3;

    ull acc[6][NH];                       // acc[tp][h] = (acc[2tp], acc[2tp+1])
    #pragma unroll
    for (int tp = 0; tp < 6; tp++)
        #pragma unroll
        for (int h = 0; h < NH; h++) acc[tp][h] = 0ull;

    union F4U { float4 f; ull u[2]; };

    // Gather + aggregate: per k, 3 contiguous LDG.128 (48B) + 24 FMA2
    #pragma unroll 1
    for (int k = 0; k < KNB; k++) {
        const int j = snb[k];
        const float4* __restrict__ rp =
            (const float4*)(g_xt + (size_t)j * 768 + b * 48 + c * 12);
        F4U u0, u1, u2;
        u0.f = rp[0];
        u1.f = rp[1];
        u2.f = rp[2];
        ull xv[6] = { u0.u[0], u0.u[1], u1.u[0], u1.u[1], u2.u[0], u2.u[1] };

        ull wp[NH];
        #pragma unroll
        for (int h = 0; h < NH; h++) {
            float wv = sw[k][h];
            wp[h] = pk2(wv, wv);
        }
        #pragma unroll
        for (int tp = 0; tp < 6; tp++)
            #pragma unroll
            for (int h = 0; h < NH; h++)
                fma2(acc[tp][h], xv[tp], wp[h], acc[tp][h]);
    }

    // Linear: y[o] = relu( sum_{t,h} acc[t][h] * W[t*4+h][o] + bias[o] )
    // packed over o-pairs (DOUT=12 -> 6 f32x2 lanes)
    ull y2[6];
    #pragma unroll
    for (int op = 0; op < 6; op++) y2[op] = pk2(sb[2 * op], sb[2 * op + 1]);

    #pragma unroll
    for (int tp = 0; tp < 6; tp++) {
        #pragma unroll
        for (int h = 0; h < NH; h++) {
            float a0, a1;
            upk2(a0, a1, acc[tp][h]);
            ull s0 = pk2(a0, a0);
            ull s1 = pk2(a1, a1);
            const ull* __restrict__ w0 =
                (const ull*)&sW[((2 * tp)     * NH + h) * DOUT];
            const ull* __restrict__ w1 =
                (const ull*)&sW[((2 * tp + 1) * NH + h) * DOUT];
            #pragma unroll
            for (int op = 0; op < 6; op++) {
                fma2(y2[op], s0, w0[op], y2[op]);
                fma2(y2[op], s1, w1[op], y2[op]);
            }
        }
    }

    // out[b][12+o][n][c]
    float* __restrict__ op_ = out + (((size_t)b * TTOT + TIN) * NN + n) * CC + c;
    #pragma unroll
    for (int op = 0; op < 6; op++) {
        float y0, y1;
        upk2(y0, y1, y2[op]);
        op_[(size_t)(2 * op)     * NN * CC] = fmaxf(y0, 0.0f);
        op_[(size_t)(2 * op + 1) * NN * CC] = fmaxf(y1, 0.0f);
    }
}

// ---------------------------------------------------------------------------
extern "C" void kernel_launch(void* const* d_in, const int* in_sizes, int n_in,
                              void* d_out, int out_size)
{
    const float* x         = (const float*)d_in[0];
    const float* dists     = (const float*)d_in[1];
    const float* W         = (const float*)d_in[2];
    const float* bias      = (const float*)d_in[3];
    const int*   neighbors = (const int*)  d_in[4];
    float* out = (float*)d_out;

    k_prep<<<(NN + NT - 1) / NT, 256>>>(x, out);
    k_main<<<NN, 64>>>(dists, W, bias, neighbors, out);
}